// round 9
// baseline (speedup 1.0000x reference)
#include <cuda_runtime.h>
#include <cstdint>

// Problem constants
#define DMK   1024          // input dim (K of the GEMM)
#define BB    8             // batch (M of the GEMM)
#define VN    32767         // internal nodes = V-1 (N of the GEMM)
#define DEPTH 15
#define TT    1024

// Phase-1 tiling: 8 warps = two k-teams of 4; each warp 64 rows (2/lane), half of K.
#define NWARPS         8
#define TEAMK          (DMK / 2)                         // 512 k per team
#define ROWS_PER_WARP  64
#define ROWS_PER_BLOCK 256                               // 4 row-groups x 64
#define KC             32                                // k-chunk per stage
#define LDW            36                                // smem row stride (conflict-free)
#define STAGES         2
#define WSTAGE         (ROWS_PER_WARP * LDW)             // 2304 floats per warp-stage
#define TILE_REGION    (NWARPS * STAGES * WSTAGE)        // 36864 floats
#define XT_REGION      (DMK * BB)                        // 8192 floats
#define XCHG_REGION    (ROWS_PER_BLOCK * BB)             // 2048 floats
#define SMEM_FLOATS    (TILE_REGION + XT_REGION + XCHG_REGION)   // 47104 = 184 KB
#define NBLOCKS        128                               // 32768 rows / 256; single wave
#define NCH            (TEAMK / KC)                      // 16 chunks per team

// Scratch: sigmoid table S[node][b] (node-major), plus grid-barrier ticket counter.
__device__ float S_buf[32768 * 8];
__device__ int   g_done = 0;   // monotone across graph replays (generation = ticket/128)

// ---------- f32x2 helpers (sm_103a packed fp32 FMA; ptxas never emits from C++) ----
__device__ __forceinline__ unsigned long long pack2(float v) {
    unsigned long long r;
    asm("mov.b64 %0, {%1, %1};" : "=l"(r) : "f"(v));
    return r;
}
__device__ __forceinline__ void ffma2(unsigned long long& d, unsigned long long a,
                                      unsigned long long b) {
    asm("fma.rn.f32x2 %0, %1, %2, %0;" : "+l"(d) : "l"(a), "l"(b));
}
__device__ __forceinline__ void unpack2(unsigned long long v, float& lo, float& hi) {
    asm("mov.b64 {%0, %1}, %2;" : "=f"(lo), "=f"(hi) : "l"(v));
}
__device__ __forceinline__ void cp16(float* sdst, const float* gsrc) {
    uint32_t s = (uint32_t)__cvta_generic_to_shared(sdst);
    asm volatile("cp.async.cg.shared.global [%0], [%1], 16;" :: "r"(s), "l"(gsrc));
}

// ============ Fused: S = sigmoid(W @ x^T + bias), then gather+product ==============
// Block = 256 threads (8 warps, 2 per SMSP so stalls overlap). Warp w owns rows
// [(w&3)*64, +64) of the block's 256 rows and k-half (w>>2). Per-warp mainloop is the
// proven R4 structure: 2 rows/lane, double-buffered cp.async, 8 f32x2 accumulators,
// no cross-lane reduction. Teams combine via an 8 KB smem exchange. A ticketed grid
// barrier (grid=128 <= 148 SMs, occ 1 -> one wave, deadlock-free) lets the first 32
// blocks do the 8192-element path-product gather inline against L2-hot S_buf.
__global__ void __launch_bounds__(256, 1)
hs_fused(const float* __restrict__ x, const float* __restrict__ W,
         const float* __restrict__ bias, const int* __restrict__ ids,
         float* __restrict__ out) {
    extern __shared__ float sm[];
    const int tid  = threadIdx.x;
    const int lane = tid & 31;
    const int warp = tid >> 5;
    const int rgrp = warp & 3;   // row group 0..3
    const int team = warp >> 2;  // k-half 0..1

    float* xT   = sm + TILE_REGION;              // xT[k][b], f32x2-pair friendly
    float* xchg = sm + TILE_REGION + XT_REGION;  // team-B partial sums [row][b]

    // Transpose x (8x1024 -> k-major, 32 KB) once per block; coalesced gmem reads.
    for (int i = tid; i < DMK * BB; i += 256) {
        int b = i >> 10;            // x is [B, DM] row-major
        int k = i & (DMK - 1);
        xT[k * 8 + b] = x[i];
    }
    __syncthreads();

    float*    wtile = sm + warp * STAGES * WSTAGE;
    const int rbw   = blockIdx.x * ROWS_PER_BLOCK + rgrp * ROWS_PER_WARP;
    const int kbase = team * TEAMK;

    // Stage one 64-row x 32-k chunk (8 KB/warp) via cp.async; rows clamped at VN-1.
    // 8 lanes cover one row's 8 k-quads -> 128 B contiguous per row, 4 rows per instr.
    auto stage = [&](int c, int s) {
        float* dst = wtile + s * WSTAGE;
        const float* src = W + kbase + c * KC;
        #pragma unroll
        for (int j = 0; j < 16; ++j) {
            int id = lane + 32 * j;          // 512 float4s per warp-chunk
            int r  = id >> 3;                // row within tile (0..63)
            int q  = id & 7;                 // k-quad (0..7)
            int gr = rbw + r;
            if (gr > VN - 1) gr = VN - 1;    // clamp: valid addr, store suppressed later
            cp16(dst + r * LDW + q * 4, src + (size_t)gr * DMK + q * 4);
        }
        asm volatile("cp.async.commit_group;");
    };

    unsigned long long acc0[4] = {0ull, 0ull, 0ull, 0ull};
    unsigned long long acc1[4] = {0ull, 0ull, 0ull, 0ull};

    stage(0, 0);
    for (int c = 0; c < NCH; ++c) {
        __syncwarp();  // all lanes done reading the slot we are about to overwrite
        if (c + 1 < NCH) {
            stage(c + 1, (c + 1) & 1);
            asm volatile("cp.async.wait_group 1;");   // chunk c complete
        } else {
            asm volatile("cp.async.wait_group 0;");
        }
        __syncwarp();  // chunk c visible to all lanes

        const float* ws = wtile + (c & 1) * WSTAGE;
        const float* xk = xT + (kbase + c * KC) * 8;

        #pragma unroll
        for (int kk = 0; kk < KC; kk += 4) {
            float4 w0 = *(const float4*)(ws + lane * LDW + kk);         // row lane
            float4 w1 = *(const float4*)(ws + (lane + 32) * LDW + kk);  // row lane+32
            float w0a[4] = {w0.x, w0.y, w0.z, w0.w};
            float w1a[4] = {w1.x, w1.y, w1.z, w1.w};
            #pragma unroll
            for (int j = 0; j < 4; ++j) {
                const double2 xab = *(const double2*)(xk + (kk + j) * 8);      // b0..b3
                const double2 xcd = *(const double2*)(xk + (kk + j) * 8 + 4);  // b4..b7
                unsigned long long x01 = __double_as_longlong(xab.x);
                unsigned long long x23 = __double_as_longlong(xab.y);
                unsigned long long x45 = __double_as_longlong(xcd.x);
                unsigned long long x67 = __double_as_longlong(xcd.y);
                unsigned long long p0 = pack2(w0a[j]);
                ffma2(acc0[0], p0, x01); ffma2(acc0[1], p0, x23);
                ffma2(acc0[2], p0, x45); ffma2(acc0[3], p0, x67);
                unsigned long long p1 = pack2(w1a[j]);
                ffma2(acc1[0], p1, x01); ffma2(acc1[1], p1, x23);
                ffma2(acc1[2], p1, x45); ffma2(acc1[3], p1, x67);
            }
        }
    }

    // Team B publishes its partial dot products to smem.
    if (team == 1) {
        #pragma unroll
        for (int rr = 0; rr < 2; ++rr) {
            const unsigned long long* acc = (rr == 0) ? acc0 : acc1;
            int rl = rgrp * 64 + lane + rr * 32;       // row within block
            float s[8];
            #pragma unroll
            for (int p = 0; p < 4; ++p) unpack2(acc[p], s[2 * p], s[2 * p + 1]);
            float4* dst = (float4*)(xchg + rl * 8);
            dst[0] = make_float4(s[0], s[1], s[2], s[3]);
            dst[1] = make_float4(s[4], s[5], s[6], s[7]);
        }
    }
    __syncthreads();

    // Team A combines, adds bias, applies sigmoid, stores S[node][0..7].
    if (team == 0) {
        #pragma unroll
        for (int rr = 0; rr < 2; ++rr) {
            int gr = rbw + lane + rr * 32;
            if (gr >= VN) continue;
            const unsigned long long* acc = (rr == 0) ? acc0 : acc1;
            int rl = rgrp * 64 + lane + rr * 32;
            const float4* prt = (const float4*)(xchg + rl * 8);
            float4 pa = prt[0], pb = prt[1];
            float bb = bias[gr];
            float s[8];
            #pragma unroll
            for (int p = 0; p < 4; ++p) unpack2(acc[p], s[2 * p], s[2 * p + 1]);
            s[0] += pa.x; s[1] += pa.y; s[2] += pa.z; s[3] += pa.w;
            s[4] += pb.x; s[5] += pb.y; s[6] += pb.z; s[7] += pb.w;
            #pragma unroll
            for (int i = 0; i < 8; ++i) {
                float z = s[i] + bb;
                s[i] = 1.0f / (1.0f + __expf(-z));
            }
            float4* dst = (float4*)(S_buf + (size_t)gr * 8);
            dst[0] = make_float4(s[0], s[1], s[2], s[3]);
            dst[1] = make_float4(s[4], s[5], s[6], s[7]);
        }
    }

    // ---- grid barrier (single wave: 128 blocks, occ 1) -------------------------
    __threadfence();        // make this block's S_buf stores visible
    __syncthreads();
    __shared__ int s_target;
    if (tid == 0) {
        int ticket = atomicAdd(&g_done, 1);             // monotone across replays
        s_target = ((ticket >> 7) + 1) << 7;            // end of this generation
    }
    __syncthreads();

    // ---- inline gather: first 32 blocks cover all 8192 outputs -----------------
    if (blockIdx.x < (BB * TT) / 256) {
        if (tid == 0) {
            while (*(volatile int*)&g_done < s_target) { }
        }
        __syncthreads();
        __threadfence();    // acquire: S_buf writes from all blocks now visible

        int idx = blockIdx.x * 256 + tid;               // < 8192
        int b   = idx >> 10;                            // ids/out are [B, T] row-major
        int m   = __ldg(ids + idx) + 32768;             // 1-based heap index of leaf
        // Heap ancestors closed-form: l-th ancestor (leaf-to-root) = (m >> l) - 1.
        float pr0 = 1.0f, pr1 = 1.0f;                   // two chains halve FMUL dep
        #pragma unroll
        for (int l = 1; l <= DEPTH; l += 2)
            pr0 *= S_buf[(size_t)((m >> l) - 1) * 8 + b];
        #pragma unroll
        for (int l = 2; l <= DEPTH; l += 2)
            pr1 *= S_buf[(size_t)((m >> l) - 1) * 8 + b];
        out[idx] = pr0 * pr1;
    }
}

// =================================== launch =======================================
extern "C" void kernel_launch(void* const* d_in, const int* in_sizes, int n_in,
                              void* d_out, int out_size) {
    // Resolve inputs by element count (robust to ordering); x precedes ids among the
    // two 8192-element inputs (setup_inputs dict order).
    const float* x = nullptr; const int* ids = nullptr;
    const float* W = nullptr; const float* bias = nullptr;
    for (int i = 0; i < n_in; ++i) {
        long long s = in_sizes[i];
        if (s == (long long)VN * DMK)       W     = (const float*)d_in[i];
        else if (s == VN)                   bias  = (const float*)d_in[i];
        else if (s == (long long)BB * TT) {
            if (!x) x = (const float*)d_in[i];
            else    ids = (const int*)d_in[i];
        }
    }

    cudaFuncSetAttribute(hs_fused, cudaFuncAttributeMaxDynamicSharedMemorySize,
                         SMEM_FLOATS * 4);
    hs_fused<<<NBLOCKS, 256, SMEM_FLOATS * 4>>>(x, W, bias, ids, (float*)d_out);
}

// round 11
// speedup vs baseline: 1.0317x; 1.0317x over previous
#include <cuda_runtime.h>
#include <cstdint>

// Problem constants
#define DMK   1024          // input dim (K of the GEMM)
#define BB    8             // batch (M of the GEMM)
#define VN    32767         // internal nodes = V-1 (N of the GEMM)
#define DEPTH 15
#define TT    1024

// Phase-1 tiling: 8 warps = two k-teams of 4; each warp 64 rows (2/lane), half of K.
#define NWARPS         8
#define TEAMK          (DMK / 2)                         // 512 k per team
#define ROWS_PER_WARP  64
#define ROWS_PER_BLOCK 256                               // 4 row-groups x 64
#define KC             32                                // k-chunk per stage
#define LDW            36                                // smem row stride (conflict-free)
#define STAGES         2
#define WSTAGE         (ROWS_PER_WARP * LDW)             // 2304 floats per warp-stage
#define TILE_REGION    (NWARPS * STAGES * WSTAGE)        // 36864 floats
#define XT_REGION      (DMK * BB)                        // 8192 floats
#define XCHG_REGION    (ROWS_PER_BLOCK * BB)             // 2048 floats
#define SMEM_FLOATS    (TILE_REGION + XT_REGION + XCHG_REGION)   // 47104 = 184 KB
#define NBLOCKS        128                               // 32768 rows / 256; single wave
#define NCH            (TEAMK / KC)                      // 16 chunks per team

// Scratch: sigmoid table S[node][b] (node-major), plus grid-barrier ticket counter.
__device__ float S_buf[32768 * 8];
__device__ int   g_done = 0;   // monotone across graph replays (generation = ticket/128)

// ---------- f32x2 helpers (sm_103a packed fp32 FMA; ptxas never emits from C++) ----
__device__ __forceinline__ unsigned long long pack2(float v) {
    unsigned long long r;
    asm("mov.b64 %0, {%1, %1};" : "=l"(r) : "f"(v));
    return r;
}
__device__ __forceinline__ void ffma2(unsigned long long& d, unsigned long long a,
                                      unsigned long long b) {
    asm("fma.rn.f32x2 %0, %1, %2, %0;" : "+l"(d) : "l"(a), "l"(b));
}
__device__ __forceinline__ void unpack2(unsigned long long v, float& lo, float& hi) {
    asm("mov.b64 {%0, %1}, %2;" : "=f"(lo), "=f"(hi) : "l"(v));
}
__device__ __forceinline__ void cp16(float* sdst, const float* gsrc) {
    uint32_t s = (uint32_t)__cvta_generic_to_shared(sdst);
    asm volatile("cp.async.cg.shared.global [%0], [%1], 16;" :: "r"(s), "l"(gsrc));
}

// ============ Fused: S = sigmoid(W @ x^T + bias), then gather+product ==============
// Block = 256 threads (8 warps, 2 per SMSP so stalls overlap). Warp w owns rows
// [(w&3)*64, +64) of the block's 256 rows and k-half (w>>2). Per-warp mainloop is the
// proven R4 structure: 2 rows/lane, double-buffered cp.async, 8 f32x2 accumulators,
// no cross-lane reduction. Teams combine via an 8 KB smem exchange. A ticketed grid
// barrier (grid=128 <= 148 SMs, occ 1 -> one wave, deadlock-free) lets the first 32
// blocks do the 8192-element path-product gather inline against L2-hot S_buf.
__global__ void __launch_bounds__(256, 1)
hs_fused(const float* __restrict__ x, const float* __restrict__ W,
         const float* __restrict__ bias, const int* __restrict__ ids,
         float* __restrict__ out) {
    extern __shared__ float sm[];
    const int tid  = threadIdx.x;
    const int lane = tid & 31;
    const int warp = tid >> 5;
    const int rgrp = warp & 3;   // row group 0..3
    const int team = warp >> 2;  // k-half 0..1

    float* xT   = sm + TILE_REGION;              // xT[k][b], f32x2-pair friendly
    float* xchg = sm + TILE_REGION + XT_REGION;  // team-B partial sums [row][b]

    // Transpose x (8x1024 -> k-major, 32 KB) once per block; coalesced gmem reads.
    for (int i = tid; i < DMK * BB; i += 256) {
        int b = i >> 10;            // x is [B, DM] row-major
        int k = i & (DMK - 1);
        xT[k * 8 + b] = x[i];
    }
    __syncthreads();

    float*    wtile = sm + warp * STAGES * WSTAGE;
    const int rbw   = blockIdx.x * ROWS_PER_BLOCK + rgrp * ROWS_PER_WARP;
    const int kbase = team * TEAMK;

    // Stage one 64-row x 32-k chunk (8 KB/warp) via cp.async; rows clamped at VN-1.
    // 8 lanes cover one row's 8 k-quads -> 128 B contiguous per row, 4 rows per instr.
    auto stage = [&](int c, int s) {
        float* dst = wtile + s * WSTAGE;
        const float* src = W + kbase + c * KC;
        #pragma unroll
        for (int j = 0; j < 16; ++j) {
            int id = lane + 32 * j;          // 512 float4s per warp-chunk
            int r  = id >> 3;                // row within tile (0..63)
            int q  = id & 7;                 // k-quad (0..7)
            int gr = rbw + r;
            if (gr > VN - 1) gr = VN - 1;    // clamp: valid addr, store suppressed later
            cp16(dst + r * LDW + q * 4, src + (size_t)gr * DMK + q * 4);
        }
        asm volatile("cp.async.commit_group;");
    };

    unsigned long long acc0[4] = {0ull, 0ull, 0ull, 0ull};
    unsigned long long acc1[4] = {0ull, 0ull, 0ull, 0ull};

    stage(0, 0);
    for (int c = 0; c < NCH; ++c) {
        __syncwarp();  // all lanes done reading the slot we are about to overwrite
        if (c + 1 < NCH) {
            stage(c + 1, (c + 1) & 1);
            asm volatile("cp.async.wait_group 1;");   // chunk c complete
        } else {
            asm volatile("cp.async.wait_group 0;");
        }
        __syncwarp();  // chunk c visible to all lanes

        const float* ws = wtile + (c & 1) * WSTAGE;
        const float* xk = xT + (kbase + c * KC) * 8;

        #pragma unroll
        for (int kk = 0; kk < KC; kk += 4) {
            float4 w0 = *(const float4*)(ws + lane * LDW + kk);         // row lane
            float4 w1 = *(const float4*)(ws + (lane + 32) * LDW + kk);  // row lane+32
            float w0a[4] = {w0.x, w0.y, w0.z, w0.w};
            float w1a[4] = {w1.x, w1.y, w1.z, w1.w};
            #pragma unroll
            for (int j = 0; j < 4; ++j) {
                const double2 xab = *(const double2*)(xk + (kk + j) * 8);      // b0..b3
                const double2 xcd = *(const double2*)(xk + (kk + j) * 8 + 4);  // b4..b7
                unsigned long long x01 = __double_as_longlong(xab.x);
                unsigned long long x23 = __double_as_longlong(xab.y);
                unsigned long long x45 = __double_as_longlong(xcd.x);
                unsigned long long x67 = __double_as_longlong(xcd.y);
                unsigned long long p0 = pack2(w0a[j]);
                ffma2(acc0[0], p0, x01); ffma2(acc0[1], p0, x23);
                ffma2(acc0[2], p0, x45); ffma2(acc0[3], p0, x67);
                unsigned long long p1 = pack2(w1a[j]);
                ffma2(acc1[0], p1, x01); ffma2(acc1[1], p1, x23);
                ffma2(acc1[2], p1, x45); ffma2(acc1[3], p1, x67);
            }
        }
    }

    // Team B publishes its partial dot products to smem.
    if (team == 1) {
        #pragma unroll
        for (int rr = 0; rr < 2; ++rr) {
            const unsigned long long* acc = (rr == 0) ? acc0 : acc1;
            int rl = rgrp * 64 + lane + rr * 32;       // row within block
            float s[8];
            #pragma unroll
            for (int p = 0; p < 4; ++p) unpack2(acc[p], s[2 * p], s[2 * p + 1]);
            float4* dst = (float4*)(xchg + rl * 8);
            dst[0] = make_float4(s[0], s[1], s[2], s[3]);
            dst[1] = make_float4(s[4], s[5], s[6], s[7]);
        }
    }
    __syncthreads();

    // Team A combines, adds bias, applies sigmoid, stores S[node][0..7].
    if (team == 0) {
        #pragma unroll
        for (int rr = 0; rr < 2; ++rr) {
            int gr = rbw + lane + rr * 32;
            if (gr >= VN) continue;
            const unsigned long long* acc = (rr == 0) ? acc0 : acc1;
            int rl = rgrp * 64 + lane + rr * 32;
            const float4* prt = (const float4*)(xchg + rl * 8);
            float4 pa = prt[0], pb = prt[1];
            float bb = bias[gr];
            float s[8];
            #pragma unroll
            for (int p = 0; p < 4; ++p) unpack2(acc[p], s[2 * p], s[2 * p + 1]);
            s[0] += pa.x; s[1] += pa.y; s[2] += pa.z; s[3] += pa.w;
            s[4] += pb.x; s[5] += pb.y; s[6] += pb.z; s[7] += pb.w;
            #pragma unroll
            for (int i = 0; i < 8; ++i) {
                float z = s[i] + bb;
                s[i] = 1.0f / (1.0f + __expf(-z));
            }
            float4* dst = (float4*)(S_buf + (size_t)gr * 8);
            dst[0] = make_float4(s[0], s[1], s[2], s[3]);
            dst[1] = make_float4(s[4], s[5], s[6], s[7]);
        }
    }

    // ---- grid barrier (single wave: 128 blocks, occ 1) -------------------------
    __threadfence();        // make this block's S_buf stores visible
    __syncthreads();
    __shared__ int s_target;
    if (tid == 0) {
        int ticket = atomicAdd(&g_done, 1);             // monotone across replays
        s_target = ((ticket >> 7) + 1) << 7;            // end of this generation
    }
    __syncthreads();

    // ---- inline gather: first 32 blocks cover all 8192 outputs -----------------
    if (blockIdx.x < (BB * TT) / 256) {
        if (tid == 0) {
            while (*(volatile int*)&g_done < s_target) { }
        }
        __syncthreads();
        __threadfence();    // acquire: S_buf writes from all blocks now visible

        int idx = blockIdx.x * 256 + tid;               // < 8192
        int b   = idx >> 10;                            // ids/out are [B, T] row-major
        int m   = __ldg(ids + idx) + 32768;             // 1-based heap index of leaf
        // Heap ancestors closed-form: l-th ancestor (leaf-to-root) = (m >> l) - 1.
        float pr0 = 1.0f, pr1 = 1.0f;                   // two chains halve FMUL dep
        #pragma unroll
        for (int l = 1; l <= DEPTH; l += 2)
            pr0 *= S_buf[(size_t)((m >> l) - 1) * 8 + b];
        #pragma unroll
        for (int l = 2; l <= DEPTH; l += 2)
            pr1 *= S_buf[(size_t)((m >> l) - 1) * 8 + b];
        out[idx] = pr0 * pr1;
    }
}

// =================================== launch =======================================
extern "C" void kernel_launch(void* const* d_in, const int* in_sizes, int n_in,
                              void* d_out, int out_size) {
    // Resolve inputs by element count (robust to ordering); x precedes ids among the
    // two 8192-element inputs (setup_inputs dict order).
    const float* x = nullptr; const int* ids = nullptr;
    const float* W = nullptr; const float* bias = nullptr;
    for (int i = 0; i < n_in; ++i) {
        long long s = in_sizes[i];
        if (s == (long long)VN * DMK)       W     = (const float*)d_in[i];
        else if (s == VN)                   bias  = (const float*)d_in[i];
        else if (s == (long long)BB * TT) {
            if (!x) x = (const float*)d_in[i];
            else    ids = (const int*)d_in[i];
        }
    }

    cudaFuncSetAttribute(hs_fused, cudaFuncAttributeMaxDynamicSharedMemorySize,
                         SMEM_FLOATS * 4);
    hs_fused<<<NBLOCKS, 256, SMEM_FLOATS * 4>>>(x, W, bias, ids, (float*)d_out);
}